// round 1
// baseline (speedup 1.0000x reference)
#include <cuda_runtime.h>

// ---------------- problem constants ----------------
#define Mdim 512
#define Ndim 1024
#define OUTER 200
#define INNER 20
#define RHO 1.0f
#define XSTEP 1e-3f

// ---------------- kernel config ----------------
#define P 128            // persistent CTAs (<=148 SMs, all co-resident)
#define NR 8             // Ndim / P  (x / G rows owned per CTA)
#define MR 4             // Mdim / P  (m-rows owned per CTA)
#define NTHREADS 256

// counters: x-version idx in [1..OUTER*INNER], r per outer, u once
#define NCTR 5120
#define CTR_R 4200
#define CTR_U 4900

// ---------------- device scratch (static allocation; no cudaMalloc) ----------------
__device__ float g_G[Ndim * Ndim];      // Gram matrix A^T A (4 MB)
__device__ float g_xbuf[2][Ndim];       // double-buffered x exchange
__device__ float g_rbuf[Mdim];
__device__ float g_ubuf[Mdim];
__device__ int   g_ctr[NCTR];

// ---------------- sync primitives (CG grid.sync pattern) ----------------
__device__ __forceinline__ void arrive_release(int* p) {
    __threadfence();                       // release prior (block-published) stores
    int one = 1;
    asm volatile("red.release.gpu.global.add.s32 [%0], %1;" :: "l"(p), "r"(one) : "memory");
}
__device__ __forceinline__ void spin_acquire(const int* p, int target) {
    int v;
    do {
        asm volatile("ld.acquire.gpu.global.s32 %0, [%1];" : "=r"(v) : "l"(p) : "memory");
    } while (v < target);
}

// ---------------- init: zero counters each launch (graph-replay safe) ----------------
__global__ void k_zero_ctr() {
    int t = blockIdx.x * blockDim.x + threadIdx.x;
    if (t < NCTR) g_ctr[t] = 0;
}

// ---------------- G = A^T A  (recomputed every launch; ~30us) ----------------
__global__ void k_gram(const float* __restrict__ A) {
    int i = blockIdx.x * 16 + threadIdx.x;   // col of G
    int j = blockIdx.y * 16 + threadIdx.y;   // row of G
    float a0 = 0.f, a1 = 0.f, a2 = 0.f, a3 = 0.f;
    for (int k = 0; k < Mdim; k += 4) {
        float aj0 = __ldg(&A[(k + 0) * Ndim + j]);
        float aj1 = __ldg(&A[(k + 1) * Ndim + j]);
        float aj2 = __ldg(&A[(k + 2) * Ndim + j]);
        float aj3 = __ldg(&A[(k + 3) * Ndim + j]);
        a0 = fmaf(aj0, __ldg(&A[(k + 0) * Ndim + i]), a0);
        a1 = fmaf(aj1, __ldg(&A[(k + 1) * Ndim + i]), a1);
        a2 = fmaf(aj2, __ldg(&A[(k + 2) * Ndim + i]), a2);
        a3 = fmaf(aj3, __ldg(&A[(k + 3) * Ndim + i]), a3);
    }
    g_G[(size_t)j * Ndim + i] = (a0 + a1) + (a2 + a3);
}

// ---------------- warp allreduce ----------------
__device__ __forceinline__ float warp_allreduce(float acc) {
#pragma unroll
    for (int off = 16; off; off >>= 1)
        acc += __shfl_xor_sync(0xffffffffu, acc, off);
    return acc;
}

// ---------------- main persistent ADMM kernel ----------------
__global__ void __launch_bounds__(NTHREADS, 1)
k_admm(const float* __restrict__ A, const float* __restrict__ b,
       const float* __restrict__ c, float* __restrict__ out) {
    extern __shared__ float sm[];
    float* Gs  = sm;                    // [NR][Ndim]  32 KB
    float* ATs = Gs  + NR * Ndim;       // [NR][Mdim]  16 KB  (A^T rows = A cols j0..j0+7)
    float* As  = ATs + NR * Mdim;       // [MR][Ndim]  16 KB  (A rows i0..i0+3)
    float* xs  = As  + MR * Ndim;       // [Ndim]       4 KB
    float* rs  = xs  + Ndim;            // [Mdim]       2 KB  (r; reused for u at end)
    float* xsl = rs  + Mdim;            // [NR] owned x values
    float* ssl = xsl + NR;              // [MR]
    float* usl = ssl + MR;              // [MR]
    float* bsl = usl + MR;              // [MR]
    float* csl = bsl + MR;              // [NR]

    const int k    = blockIdx.x;
    const int tid  = threadIdx.x;
    const int w    = tid >> 5;
    const int lane = tid & 31;
    const int j0   = k * NR;            // owned n-range
    const int i0   = k * MR;            // owned m-range

    // ---- stage everything into smem ----
    {
        const float4* gsrc = reinterpret_cast<const float4*>(g_G + (size_t)j0 * Ndim);
        float4*       gdst = reinterpret_cast<float4*>(Gs);
        for (int t = tid; t < NR * Ndim / 4; t += NTHREADS) gdst[t] = gsrc[t];

        const float4* asrc = reinterpret_cast<const float4*>(A + (size_t)i0 * Ndim);
        float4*       adst = reinterpret_cast<float4*>(As);
        for (int t = tid; t < MR * Ndim / 4; t += NTHREADS) adst[t] = asrc[t];

        for (int t = tid; t < NR * Mdim; t += NTHREADS) {
            int i = t >> 3, r = t & 7;
            ATs[r * Mdim + i] = A[(size_t)i * Ndim + j0 + r];
        }
        for (int t = tid; t < Ndim; t += NTHREADS) xs[t] = 0.f;
        if (tid < MR) { ssl[tid] = 0.f; usl[tid] = 0.f; bsl[tid] = b[i0 + tid]; }
        if (tid < NR) { xsl[tid] = 0.f; csl[tid] = c[j0 + tid]; }
    }
    __syncthreads();

    float h = 0.f;  // (A^T r)[j0+w], held per-thread for warp w's row

    for (int o = 0; o < OUTER; o++) {
        // ---- r = s + b - u : exchange m-slices ----
        if (tid < MR) g_rbuf[i0 + tid] = ssl[tid] + bsl[tid] - usl[tid];
        __syncthreads();
        if (tid == 0) { arrive_release(&g_ctr[CTR_R + o]); spin_acquire(&g_ctr[CTR_R + o], P); }
        __syncthreads();
        for (int t = tid; t < Mdim; t += NTHREADS) rs[t] = g_rbuf[t];
        __syncthreads();

        // ---- h = (A^T r) slice : warp w handles row j0+w ----
        {
            const float4* ap = reinterpret_cast<const float4*>(ATs + w * Mdim);
            const float4* rp = reinterpret_cast<const float4*>(rs);
            float acc = 0.f;
#pragma unroll
            for (int q = 0; q < Mdim / 128; q++) {
                float4 a4 = ap[lane + 32 * q], r4 = rp[lane + 32 * q];
                acc = fmaf(a4.x, r4.x, acc); acc = fmaf(a4.y, r4.y, acc);
                acc = fmaf(a4.z, r4.z, acc); acc = fmaf(a4.w, r4.w, acc);
            }
            h = warp_allreduce(acc);
        }

        // ---- inner projected-GD loop: one global x-exchange per step ----
        for (int t = 0; t < INNER; t++) {
            int idx = o * INNER + t;                // x version being consumed
            if (t > 0) {
                if (tid == 0) spin_acquire(&g_ctr[idx], P);
                __syncthreads();
                const float* src = g_xbuf[idx & 1];
                for (int q = tid; q < Ndim; q += NTHREADS) xs[q] = src[q];
                __syncthreads();
            }
            // g = (G x)[j0+w]
            float acc = 0.f;
            const float4* gp = reinterpret_cast<const float4*>(Gs + w * Ndim);
            const float4* xp = reinterpret_cast<const float4*>(xs);
#pragma unroll
            for (int q = 0; q < Ndim / 128; q++) {
                float4 g4 = gp[lane + 32 * q], x4 = xp[lane + 32 * q];
                acc = fmaf(g4.x, x4.x, acc); acc = fmaf(g4.y, x4.y, acc);
                acc = fmaf(g4.z, x4.z, acc); acc = fmaf(g4.w, x4.w, acc);
            }
            acc = warp_allreduce(acc);
            if (lane == 0) {
                float grad = csl[w] + RHO * (acc - h);
                float xv = fmaxf(xsl[w] - XSTEP * grad, 0.f);
                xsl[w] = xv;
                g_xbuf[(idx + 1) & 1][j0 + w] = xv;   // publish new slice
            }
            __syncthreads();
            if (tid == 0) arrive_release(&g_ctr[idx + 1]);
        }

        // ---- pull final x of this outer step ----
        {
            int idx = o * INNER + INNER;
            if (tid == 0) spin_acquire(&g_ctr[idx], P);
            __syncthreads();
            const float* src = g_xbuf[idx & 1];
            for (int q = tid; q < Ndim; q += NTHREADS) xs[q] = src[q];
            __syncthreads();
        }

        // ---- Ax slice + s,u updates (warps 0..3, row i0+w) ----
        if (w < MR) {
            const float4* apr = reinterpret_cast<const float4*>(As + w * Ndim);
            const float4* xp  = reinterpret_cast<const float4*>(xs);
            float acc = 0.f;
#pragma unroll
            for (int q = 0; q < Ndim / 128; q++) {
                float4 a4 = apr[lane + 32 * q], x4 = xp[lane + 32 * q];
                acc = fmaf(a4.x, x4.x, acc); acc = fmaf(a4.y, x4.y, acc);
                acc = fmaf(a4.z, x4.z, acc); acc = fmaf(a4.w, x4.w, acc);
            }
            acc = warp_allreduce(acc);
            if (lane == 0) {
                float ax = acc, u = usl[w], bb = bsl[w];
                float s = fmaxf(ax - bb + u, 0.f);
                u = u + (ax - s - bb);
                ssl[w] = s; usl[w] = u;
            }
        }
        __syncthreads();
    }

    // ---- epilogue: lambda = max(-rho*u,0), nu = max(c + A^T(rho*u), 0) ----
    if (tid < MR) g_ubuf[i0 + tid] = usl[tid];
    __syncthreads();
    if (tid == 0) { arrive_release(&g_ctr[CTR_U]); spin_acquire(&g_ctr[CTR_U], P); }
    __syncthreads();
    for (int t = tid; t < Mdim; t += NTHREADS) rs[t] = g_ubuf[t];
    __syncthreads();

    if (tid < NR) out[j0 + tid] = xs[j0 + tid];                          // x
    if (tid < MR) {
        out[Ndim + i0 + tid]            = ssl[tid];                      // s
        out[Ndim + Mdim + i0 + tid]     = usl[tid];                      // u
        out[Ndim + 2 * Mdim + i0 + tid] = fmaxf(-RHO * usl[tid], 0.f);   // lambda
    }
    {
        const float4* ap = reinterpret_cast<const float4*>(ATs + w * Mdim);
        const float4* up = reinterpret_cast<const float4*>(rs);
        float acc = 0.f;
#pragma unroll
        for (int q = 0; q < Mdim / 128; q++) {
            float4 a4 = ap[lane + 32 * q], u4 = up[lane + 32 * q];
            acc = fmaf(a4.x, u4.x, acc); acc = fmaf(a4.y, u4.y, acc);
            acc = fmaf(a4.z, u4.z, acc); acc = fmaf(a4.w, u4.w, acc);
        }
        acc = warp_allreduce(acc);
        if (lane == 0)
            out[Ndim + 3 * Mdim + j0 + w] = fmaxf(csl[w] + RHO * acc, 0.f);  // nu
    }
}

// ---------------- launch ----------------
extern "C" void kernel_launch(void* const* d_in, const int* in_sizes, int n_in,
                              void* d_out, int out_size) {
    const float *A = nullptr, *b = nullptr, *c = nullptr;
    for (int i = 0; i < n_in; i++) {
        if (in_sizes[i] == Mdim * Ndim)      A = (const float*)d_in[i];
        else if (in_sizes[i] == Mdim)        b = (const float*)d_in[i];
        else if (in_sizes[i] == Ndim)        c = (const float*)d_in[i];
    }
    (void)out_size;

    const int smem_bytes = (NR * Ndim + NR * Mdim + MR * Ndim + Ndim + Mdim
                            + NR + MR + MR + MR + NR) * (int)sizeof(float);
    cudaFuncSetAttribute(k_admm, cudaFuncAttributeMaxDynamicSharedMemorySize, smem_bytes);

    k_zero_ctr<<<(NCTR + 255) / 256, 256>>>();
    dim3 gb(16, 16), gg(Ndim / 16, Ndim / 16);
    k_gram<<<gg, gb>>>(A);
    k_admm<<<P, NTHREADS, smem_bytes>>>(A, b, c, (float*)d_out);
}

// round 2
// speedup vs baseline: 1.5804x; 1.5804x over previous
#include <cuda_runtime.h>

// ---------------- problem constants ----------------
#define Mdim 512
#define Ndim 1024
#define OUTER 200
#define INNER 20
#define RHO 1.0f
#define XSTEP 1e-3f

// ---------------- kernel config ----------------
#define P 128            // persistent CTAs, one per SM (<=148)
#define NR 8             // Ndim / P : x/G rows owned per CTA
#define MR 4             // Mdim / P : m rows owned per CTA
#define NTHREADS 256
#define XPT (Ndim / NTHREADS)   // 4 x-elements per thread
#define RPT (Mdim / NTHREADS)   // 2 r-elements per thread

// ---------------- device scratch (no cudaMalloc) ----------------
__device__ float g_G[Ndim * Ndim];                 // Gram A^T A
__device__ unsigned long long g_xtag[2][Ndim];     // tagged x exchange {val,seq}
__device__ unsigned long long g_rtag[2][Mdim];     // tagged r/u exchange

// ---------------- tagged 8B atomics (fence-free exchange) ----------------
__device__ __forceinline__ unsigned long long pack_val(float v, int seq) {
    return (unsigned long long)__float_as_uint(v) |
           ((unsigned long long)(unsigned)seq << 32);
}
__device__ __forceinline__ void st_tag(unsigned long long* p, unsigned long long v) {
    asm volatile("st.relaxed.gpu.global.b64 [%0], %1;" :: "l"(p), "l"(v) : "memory");
}
__device__ __forceinline__ unsigned long long ld_tag(const unsigned long long* p) {
    unsigned long long v;
    asm volatile("ld.relaxed.gpu.global.b64 %0, [%1];" : "=l"(v) : "l"(p) : "memory");
    return v;
}

// ---------------- init: reset tags each launch (graph-replay safe) ----------------
__global__ void k_init_tags() {
    int t = blockIdx.x * blockDim.x + threadIdx.x;
    if (t < 2 * Ndim) ((unsigned long long*)g_xtag)[t] = 0ull;
    if (t < 2 * Mdim) ((unsigned long long*)g_rtag)[t] = 0ull;
}

// ---------------- G = A^T A ----------------
__global__ void k_gram(const float* __restrict__ A) {
    int i = blockIdx.x * 16 + threadIdx.x;
    int j = blockIdx.y * 16 + threadIdx.y;
    float a0 = 0.f, a1 = 0.f, a2 = 0.f, a3 = 0.f;
    for (int k = 0; k < Mdim; k += 4) {
        float aj0 = __ldg(&A[(k + 0) * Ndim + j]);
        float aj1 = __ldg(&A[(k + 1) * Ndim + j]);
        float aj2 = __ldg(&A[(k + 2) * Ndim + j]);
        float aj3 = __ldg(&A[(k + 3) * Ndim + j]);
        a0 = fmaf(aj0, __ldg(&A[(k + 0) * Ndim + i]), a0);
        a1 = fmaf(aj1, __ldg(&A[(k + 1) * Ndim + i]), a1);
        a2 = fmaf(aj2, __ldg(&A[(k + 2) * Ndim + i]), a2);
        a3 = fmaf(aj3, __ldg(&A[(k + 3) * Ndim + i]), a3);
    }
    g_G[(size_t)j * Ndim + i] = (a0 + a1) + (a2 + a3);
}

__device__ __forceinline__ float warp_allreduce(float acc) {
#pragma unroll
    for (int off = 16; off; off >>= 1)
        acc += __shfl_xor_sync(0xffffffffu, acc, off);
    return acc;
}

// ---------------- main persistent ADMM kernel ----------------
__global__ void __launch_bounds__(NTHREADS, 1)
k_admm(const float* __restrict__ A, const float* __restrict__ b,
       const float* __restrict__ c, float* __restrict__ out) {
    __shared__ float part[NR][NTHREADS];   // 8 KB cross-thread partials
    __shared__ float ATs[NR][Mdim];        // 16 KB: A^T rows (A cols j0..j0+7)
    __shared__ float rs[Mdim];             // 2 KB: r (reused for u at epilogue)

    const int k    = blockIdx.x;
    const int tid  = threadIdx.x;
    const int w    = tid >> 5;
    const int lane = tid & 31;
    const int j0   = k * NR;
    const int i0   = k * MR;

    // ---- register-resident matrix chunks (iteration-invariant) ----
    float4 Gr[NR];   // Gr[r] = G[j0+r][tid*4 .. +3]
#pragma unroll
    for (int r = 0; r < NR; r++)
        Gr[r] = *reinterpret_cast<const float4*>(g_G + (size_t)(j0 + r) * Ndim + tid * XPT);
    float4 Arw[MR];  // Arw[r] = A[i0+r][tid*4 .. +3]
#pragma unroll
    for (int r = 0; r < MR; r++)
        Arw[r] = *reinterpret_cast<const float4*>(A + (size_t)(i0 + r) * Ndim + tid * XPT);

    // ---- stage A^T rows into smem (used once per outer + epilogue) ----
    for (int t = tid; t < NR * Mdim; t += NTHREADS) {
        int i = t >> 3, r = t & 7;
        ATs[r][i] = A[(size_t)i * Ndim + j0 + r];
    }

    // ---- per-thread / per-lane0 state ----
    float xr[XPT];
#pragma unroll
    for (int e = 0; e < XPT; e++) xr[e] = 0.f;     // x_0 = 0
    float xval = 0.f, cval = 0.f, hval = 0.f;      // row-owner state (lane0 of warp w)
    if (lane == 0) cval = c[j0 + w];
    float sv = 0.f, uv = 0.f, bv = 0.f;            // m-row state (lane0 of warps 0..3)
    if (lane == 0 && w < MR) bv = b[i0 + w];

    __syncthreads();

    for (int o = 0; o < OUTER; o++) {
        // ---- publish r = s + b - u (tag o+1), then poll full r into smem ----
        if (lane == 0 && w < MR)
            st_tag(&g_rtag[(o + 1) & 1][i0 + w], pack_val(sv + bv - uv, o + 1));
        {
            const int want = o + 1;
            unsigned long long* buf = g_rtag[(o + 1) & 1];
            int e0 = tid, e1 = tid + NTHREADS;
            bool d0 = false, d1 = false;
            while (!(d0 && d1)) {
                if (!d0) { unsigned long long v = ld_tag(buf + e0);
                    if ((int)(v >> 32) == want) { rs[e0] = __uint_as_float((unsigned)v); d0 = true; } }
                if (!d1) { unsigned long long v = ld_tag(buf + e1);
                    if ((int)(v >> 32) == want) { rs[e1] = __uint_as_float((unsigned)v); d1 = true; } }
            }
        }
        __syncthreads();

        // ---- h = (A^T r)[j0+w] : row-per-warp over smem ----
        {
            const float4* ap = reinterpret_cast<const float4*>(ATs[w]);
            const float4* rp = reinterpret_cast<const float4*>(rs);
            float a0 = 0.f, a1 = 0.f, a2 = 0.f, a3 = 0.f;
#pragma unroll
            for (int q = 0; q < Mdim / 128; q++) {
                float4 a4 = ap[lane + 32 * q], r4 = rp[lane + 32 * q];
                a0 = fmaf(a4.x, r4.x, a0); a1 = fmaf(a4.y, r4.y, a1);
                a2 = fmaf(a4.z, r4.z, a2); a3 = fmaf(a4.w, r4.w, a3);
            }
            float s = warp_allreduce((a0 + a1) + (a2 + a3));
            if (lane == 0) hval = s;
        }

        // ---- inner projected-GD: one fence-free tagged exchange per step ----
        for (int t = 0; t < INNER; t++) {
            const int seq = o * INNER + t;

            // per-thread partials of (G x) over register chunks
#pragma unroll
            for (int r = 0; r < NR; r++) {
                float a = Gr[r].x * xr[0];
                a = fmaf(Gr[r].y, xr[1], a);
                a = fmaf(Gr[r].z, xr[2], a);
                a = fmaf(Gr[r].w, xr[3], a);
                part[r][tid] = a;
            }
            __syncthreads();

            // warp w reduces row w, lane0 updates + publishes (tag seq+1)
            {
                float s = 0.f;
#pragma unroll
                for (int j = 0; j < NTHREADS / 32; j++) s += part[w][lane + 32 * j];
                s = warp_allreduce(s);
                if (lane == 0) {
                    float grad = cval + RHO * (s - hval);
                    xval = fmaxf(xval - XSTEP * grad, 0.f);
                    st_tag(&g_xtag[(seq + 1) & 1][j0 + w], pack_val(xval, seq + 1));
                }
            }

            // poll x_{seq+1} straight into registers (no smem, no fence)
            {
                const int want = seq + 1;
                unsigned long long* buf = g_xtag[(seq + 1) & 1] + tid * XPT;
                unsigned pend = (1u << XPT) - 1;
                while (pend) {
#pragma unroll
                    for (int e = 0; e < XPT; e++) {
                        if (pend & (1u << e)) {
                            unsigned long long v = ld_tag(buf + e);
                            if ((int)(v >> 32) == want) {
                                xr[e] = __uint_as_float((unsigned)v);
                                pend &= ~(1u << e);
                            }
                        }
                    }
                }
            }
            __syncthreads();   // protects part[] reuse next iteration
        }

        // ---- Ax partials on register A rows, reduce, s/u update ----
        {
#pragma unroll
            for (int r = 0; r < MR; r++) {
                float a = Arw[r].x * xr[0];
                a = fmaf(Arw[r].y, xr[1], a);
                a = fmaf(Arw[r].z, xr[2], a);
                a = fmaf(Arw[r].w, xr[3], a);
                part[r][tid] = a;
            }
            __syncthreads();
            if (w < MR) {
                float s2 = 0.f;
#pragma unroll
                for (int j = 0; j < NTHREADS / 32; j++) s2 += part[w][lane + 32 * j];
                s2 = warp_allreduce(s2);
                if (lane == 0) {
                    float ax = s2;
                    float snew = fmaxf(ax - bv + uv, 0.f);
                    uv = uv + (ax - snew - bv);
                    sv = snew;
                }
            }
        }
        // (part[] reuse next outer is protected by the sync after the r-poll)
    }

    // ---------------- epilogue ----------------
    // publish u (tag OUTER+1), poll into rs
    if (lane == 0 && w < MR)
        st_tag(&g_rtag[(OUTER + 1) & 1][i0 + w], pack_val(uv, OUTER + 1));
    {
        const int want = OUTER + 1;
        unsigned long long* buf = g_rtag[(OUTER + 1) & 1];
        int e0 = tid, e1 = tid + NTHREADS;
        bool d0 = false, d1 = false;
        while (!(d0 && d1)) {
            if (!d0) { unsigned long long v = ld_tag(buf + e0);
                if ((int)(v >> 32) == want) { rs[e0] = __uint_as_float((unsigned)v); d0 = true; } }
            if (!d1) { unsigned long long v = ld_tag(buf + e1);
                if ((int)(v >> 32) == want) { rs[e1] = __uint_as_float((unsigned)v); d1 = true; } }
        }
    }
    __syncthreads();

    // x output: thread tid owns x[tid*4 .. +3]; CTA k writes x[8k..8k+7]
    if ((tid >> 1) == k) {
        int base = (tid & 1) * XPT;
#pragma unroll
        for (int e = 0; e < XPT; e++) out[j0 + base + e] = xr[e];
    }
    if (lane == 0 && w < MR) {
        out[Ndim + i0 + w]            = sv;                       // s
        out[Ndim + Mdim + i0 + w]     = uv;                       // u
        out[Ndim + 2 * Mdim + i0 + w] = fmaxf(-RHO * uv, 0.f);    // lambda
    }
    // nu = max(c + rho * A^T u, 0) : row-per-warp
    {
        const float4* ap = reinterpret_cast<const float4*>(ATs[w]);
        const float4* up = reinterpret_cast<const float4*>(rs);
        float a0 = 0.f, a1 = 0.f, a2 = 0.f, a3 = 0.f;
#pragma unroll
        for (int q = 0; q < Mdim / 128; q++) {
            float4 a4 = ap[lane + 32 * q], u4 = up[lane + 32 * q];
            a0 = fmaf(a4.x, u4.x, a0); a1 = fmaf(a4.y, u4.y, a1);
            a2 = fmaf(a4.z, u4.z, a2); a3 = fmaf(a4.w, u4.w, a3);
        }
        float s = warp_allreduce((a0 + a1) + (a2 + a3));
        if (lane == 0)
            out[Ndim + 3 * Mdim + j0 + w] = fmaxf(cval + RHO * s, 0.f);
    }
}

// ---------------- launch ----------------
extern "C" void kernel_launch(void* const* d_in, const int* in_sizes, int n_in,
                              void* d_out, int out_size) {
    const float *A = nullptr, *b = nullptr, *c = nullptr;
    for (int i = 0; i < n_in; i++) {
        if (in_sizes[i] == Mdim * Ndim)      A = (const float*)d_in[i];
        else if (in_sizes[i] == Mdim)        b = (const float*)d_in[i];
        else if (in_sizes[i] == Ndim)        c = (const float*)d_in[i];
    }
    (void)out_size;

    k_init_tags<<<(2 * Ndim + 255) / 256, 256>>>();
    dim3 gb(16, 16), gg(Ndim / 16, Ndim / 16);
    k_gram<<<gg, gb>>>(A);
    k_admm<<<P, NTHREADS>>>(A, b, c, (float*)d_out);
}